// round 8
// baseline (speedup 1.0000x reference)
#include <cuda_runtime.h>

// Fused confusion-matrix reduction.
//   y_pred, y_true: [16, 3, 512, 512] f32 -> out [B*C, 4] = [tp, tn, fp, fn]
// tp = sum(p*t); fp = sum(p) - tp; fn = sum(t) - tp; tn = N - sum(p) - sum(t) + tp.
// Single kernel: grid-wide streaming reduce + last-block finalize
// (threadFenceReduction pattern) to avoid a latency-bound tail kernel.

#define SLICES 48                       // B*C
#define N_PER_SLICE (512 * 512)         // 262144 elements per slice
#define BLOCKS_PER_SLICE 32
#define THREADS 256
#define NBLOCKS (SLICES * BLOCKS_PER_SLICE)                       // 1536
#define VECS_PER_BLOCK (N_PER_SLICE / BLOCKS_PER_SLICE / 4)       // 2048 float4
#define VECS_PER_THREAD (VECS_PER_BLOCK / THREADS)                // 8

// Per-block partials: [block][3] = {sum_p, sum_t, sum_pt}.
// Every slot overwritten each launch -> deterministic, graph-replay safe.
__device__ float g_part[NBLOCKS * 3];
__device__ unsigned int g_ticket = 0;   // reset to 0 by last block each launch

__global__ __launch_bounds__(THREADS)
void cm_fused_kernel(const float4* __restrict__ p4, const float4* __restrict__ t4,
                     float* __restrict__ out) {
    const int blk = blockIdx.x;                         // 0 .. 1535
    const long base = (long)blk * VECS_PER_BLOCK + threadIdx.x;

    float sp = 0.0f, st = 0.0f, spt = 0.0f;

#pragma unroll
    for (int i = 0; i < VECS_PER_THREAD; i++) {
        const float4 pv = __ldg(&p4[base + (long)i * THREADS]);
        const float4 tv = __ldg(&t4[base + (long)i * THREADS]);
        sp  += (pv.x + pv.y) + (pv.z + pv.w);
        st  += (tv.x + tv.y) + (tv.z + tv.w);
        spt += pv.x * tv.x + pv.y * tv.y + pv.z * tv.z + pv.w * tv.w;
    }

    // Intra-block tree reduction (warp shuffles + smem).
#pragma unroll
    for (int off = 16; off > 0; off >>= 1) {
        sp  += __shfl_down_sync(0xFFFFFFFFu, sp,  off);
        st  += __shfl_down_sync(0xFFFFFFFFu, st,  off);
        spt += __shfl_down_sync(0xFFFFFFFFu, spt, off);
    }

    __shared__ float sm[3][THREADS / 32];
    const int wid = threadIdx.x >> 5;
    const int lid = threadIdx.x & 31;
    if (lid == 0) {
        sm[0][wid] = sp;
        sm[1][wid] = st;
        sm[2][wid] = spt;
    }
    __syncthreads();

    __shared__ bool amLast;
    if (threadIdx.x == 0) {
        float a = 0.0f, b = 0.0f, c = 0.0f;
#pragma unroll
        for (int w = 0; w < THREADS / 32; w++) {
            a += sm[0][w];
            b += sm[1][w];
            c += sm[2][w];
        }
        g_part[blk * 3 + 0] = a;
        g_part[blk * 3 + 1] = b;
        g_part[blk * 3 + 2] = c;
        // Make partials visible before taking a ticket.
        __threadfence();
        unsigned int t = atomicAdd(&g_ticket, 1u);
        amLast = (t == (unsigned int)(NBLOCKS - 1));
    }
    __syncthreads();

    if (!amLast) return;

    // ---- Last-block finalize: 8 warps, each handles 6 slices. ----
    // Warp w handles slices w, w+8, ..., w+40. Lane l reads the partial of
    // per-slice block l, shuffle-reduces in double for the final combine.
#pragma unroll
    for (int g = 0; g < SLICES / (THREADS / 32); g++) {
        const int s = g * (THREADS / 32) + wid;         // slice index
        const int idx = (s * BLOCKS_PER_SLICE + lid) * 3;
        double a = (double)g_part[idx + 0];
        double b = (double)g_part[idx + 1];
        double c = (double)g_part[idx + 2];
#pragma unroll
        for (int off = 16; off > 0; off >>= 1) {
            a += __shfl_down_sync(0xFFFFFFFFu, a, off);
            b += __shfl_down_sync(0xFFFFFFFFu, b, off);
            c += __shfl_down_sync(0xFFFFFFFFu, c, off);
        }
        if (lid == 0) {
            const double n = (double)N_PER_SLICE;
            out[s * 4 + 0] = (float)c;                  // tp
            out[s * 4 + 1] = (float)(n - a - b + c);    // tn
            out[s * 4 + 2] = (float)(a - c);            // fp
            out[s * 4 + 3] = (float)(b - c);            // fn
        }
    }

    // Reset ticket for the next graph replay (only last block runs this;
    // no other block can be concurrently ticketing since all have arrived).
    if (threadIdx.x == 0) g_ticket = 0;
}

extern "C" void kernel_launch(void* const* d_in, const int* in_sizes, int n_in,
                              void* d_out, int out_size) {
    const float4* p4 = (const float4*)d_in[0];   // y_pred
    const float4* t4 = (const float4*)d_in[1];   // y_true
    float* out = (float*)d_out;

    cm_fused_kernel<<<NBLOCKS, THREADS>>>(p4, t4, out);
}

// round 9
// speedup vs baseline: 1.0105x; 1.0105x over previous
#include <cuda_runtime.h>

// Fused confusion-matrix reduction.
//   y_pred, y_true: [16, 3, 512, 512] f32 -> out [B*C, 4] = [tp, tn, fp, fn]
// tp = sum(p*t); fp = sum(p) - tp; fn = sum(t) - tp; tn = N - sum(p) - sum(t) + tp.
//
// Two kernels: (1) streaming reduce, NO fences/atomics in or after the hot
// loop (a gpu-scope threadfence per block emits CCTL.IVALL = L1D invalidate,
// which stalled co-resident streaming blocks and cost 6+ us in R8);
// (2) warp-parallel finalize (lane-per-partial shuffle reduce, ~us-scale).

#define SLICES 48                       // B*C
#define N_PER_SLICE (512 * 512)         // 262144 elements per slice
#define BLOCKS_PER_SLICE 32
#define THREADS 256
#define NBLOCKS (SLICES * BLOCKS_PER_SLICE)                       // 1536
#define VECS_PER_BLOCK (N_PER_SLICE / BLOCKS_PER_SLICE / 4)       // 2048 float4
#define VECS_PER_THREAD (VECS_PER_BLOCK / THREADS)                // 8

// Per-block partials: [block][3] = {sum_p, sum_t, sum_pt}.
// Every slot is overwritten each launch -> deterministic, graph-replay safe.
__device__ float g_part[NBLOCKS * 3];

__global__ __launch_bounds__(THREADS)
void cm_reduce_kernel(const float4* __restrict__ p4, const float4* __restrict__ t4) {
    const int blk = blockIdx.x;                         // 0 .. 1535
    const long base = (long)blk * VECS_PER_BLOCK + threadIdx.x;

    float sp = 0.0f, st = 0.0f, spt = 0.0f;

#pragma unroll
    for (int i = 0; i < VECS_PER_THREAD; i++) {
        const float4 pv = __ldg(&p4[base + (long)i * THREADS]);
        const float4 tv = __ldg(&t4[base + (long)i * THREADS]);
        sp  += (pv.x + pv.y) + (pv.z + pv.w);
        st  += (tv.x + tv.y) + (tv.z + tv.w);
        spt += pv.x * tv.x + pv.y * tv.y + pv.z * tv.z + pv.w * tv.w;
    }

    // Intra-block tree reduction (warp shuffles + smem).
#pragma unroll
    for (int off = 16; off > 0; off >>= 1) {
        sp  += __shfl_down_sync(0xFFFFFFFFu, sp,  off);
        st  += __shfl_down_sync(0xFFFFFFFFu, st,  off);
        spt += __shfl_down_sync(0xFFFFFFFFu, spt, off);
    }

    __shared__ float sm[3][THREADS / 32];
    const int wid = threadIdx.x >> 5;
    const int lid = threadIdx.x & 31;
    if (lid == 0) {
        sm[0][wid] = sp;
        sm[1][wid] = st;
        sm[2][wid] = spt;
    }
    __syncthreads();

    if (threadIdx.x == 0) {
        float a = 0.0f, b = 0.0f, c = 0.0f;
#pragma unroll
        for (int w = 0; w < THREADS / 32; w++) {
            a += sm[0][w];
            b += sm[1][w];
            c += sm[2][w];
        }
        g_part[blk * 3 + 0] = a;
        g_part[blk * 3 + 1] = b;
        g_part[blk * 3 + 2] = c;
    }
}

// Warp-parallel finalize: 8 warps, each handles 6 slices. Lane l holds the
// partials of per-slice block l; 5 double shuffles fold the 32 partials.
__global__ __launch_bounds__(THREADS)
void cm_finalize_kernel(float* __restrict__ out) {
    const int wid = threadIdx.x >> 5;
    const int lid = threadIdx.x & 31;

#pragma unroll
    for (int g = 0; g < SLICES / (THREADS / 32); g++) {
        const int s = g * (THREADS / 32) + wid;         // slice index
        const int idx = (s * BLOCKS_PER_SLICE + lid) * 3;
        double a = (double)g_part[idx + 0];
        double b = (double)g_part[idx + 1];
        double c = (double)g_part[idx + 2];
#pragma unroll
        for (int off = 16; off > 0; off >>= 1) {
            a += __shfl_down_sync(0xFFFFFFFFu, a, off);
            b += __shfl_down_sync(0xFFFFFFFFu, b, off);
            c += __shfl_down_sync(0xFFFFFFFFu, c, off);
        }
        if (lid == 0) {
            const double n = (double)N_PER_SLICE;
            out[s * 4 + 0] = (float)c;                  // tp
            out[s * 4 + 1] = (float)(n - a - b + c);    // tn
            out[s * 4 + 2] = (float)(a - c);            // fp
            out[s * 4 + 3] = (float)(b - c);            // fn
        }
    }
}

extern "C" void kernel_launch(void* const* d_in, const int* in_sizes, int n_in,
                              void* d_out, int out_size) {
    const float4* p4 = (const float4*)d_in[0];   // y_pred
    const float4* t4 = (const float4*)d_in[1];   // y_true
    float* out = (float*)d_out;

    cm_reduce_kernel<<<NBLOCKS, THREADS>>>(p4, t4);
    cm_finalize_kernel<<<1, THREADS>>>(out);
}

// round 10
// speedup vs baseline: 1.4948x; 1.4792x over previous
#include <cuda_runtime.h>
#include <cuda_device_runtime_api.h>

// Fused confusion-matrix reduction.
//   y_pred, y_true: [16, 3, 512, 512] f32 -> out [B*C, 4] = [tp, tn, fp, fn]
// tp = sum(p*t); fp = sum(p) - tp; fn = sum(t) - tp; tn = N - sum(p) - sum(t) + tp.
//
// Kernel 1: pure streaming reduce (no fences/atomics — gpu-scope fences emit
// CCTL.IVALL and poisoned the stream in R8). Kernel 2: tiny finalize,
// launched with PDL (programmatic stream serialization) so its launch/spin-up
// overlaps kernel 1 instead of serializing after it.

#define SLICES 48                       // B*C
#define N_PER_SLICE (512 * 512)         // 262144 elements per slice
#define BLOCKS_PER_SLICE 32
#define THREADS 256
#define NBLOCKS (SLICES * BLOCKS_PER_SLICE)                       // 1536
#define VECS_PER_BLOCK (N_PER_SLICE / BLOCKS_PER_SLICE / 4)       // 2048 float4
#define VECS_PER_THREAD (VECS_PER_BLOCK / THREADS)                // 8

// Per-block partials: [block][3] = {sum_p, sum_t, sum_pt}.
// Every slot overwritten each launch -> deterministic, graph-replay safe.
__device__ float g_part[NBLOCKS * 3];

__global__ __launch_bounds__(THREADS)
void cm_reduce_kernel(const float4* __restrict__ p4, const float4* __restrict__ t4) {
    const int blk = blockIdx.x;                         // 0 .. 1535
    const long base = (long)blk * VECS_PER_BLOCK + threadIdx.x;

    float sp = 0.0f, st = 0.0f, spt = 0.0f;

#pragma unroll
    for (int i = 0; i < VECS_PER_THREAD; i++) {
        const float4 pv = __ldg(&p4[base + (long)i * THREADS]);
        const float4 tv = __ldg(&t4[base + (long)i * THREADS]);
        sp  += (pv.x + pv.y) + (pv.z + pv.w);
        st  += (tv.x + tv.y) + (tv.z + tv.w);
        spt += pv.x * tv.x + pv.y * tv.y + pv.z * tv.z + pv.w * tv.w;
    }

    // Intra-block tree reduction (warp shuffles + smem).
#pragma unroll
    for (int off = 16; off > 0; off >>= 1) {
        sp  += __shfl_down_sync(0xFFFFFFFFu, sp,  off);
        st  += __shfl_down_sync(0xFFFFFFFFu, st,  off);
        spt += __shfl_down_sync(0xFFFFFFFFu, spt, off);
    }

    __shared__ float sm[3][THREADS / 32];
    const int wid = threadIdx.x >> 5;
    const int lid = threadIdx.x & 31;
    if (lid == 0) {
        sm[0][wid] = sp;
        sm[1][wid] = st;
        sm[2][wid] = spt;
    }
    __syncthreads();

    if (threadIdx.x == 0) {
        float a = 0.0f, b = 0.0f, c = 0.0f;
#pragma unroll
        for (int w = 0; w < THREADS / 32; w++) {
            a += sm[0][w];
            b += sm[1][w];
            c += sm[2][w];
        }
        g_part[blk * 3 + 0] = a;
        g_part[blk * 3 + 1] = b;
        g_part[blk * 3 + 2] = c;
    }
}

// Warp-parallel finalize: 8 warps x 6 slices each; lane l folds the partial
// of per-slice block l via float shuffles; final combine in double.
// Launched with PDL: starts alongside the reduce, blocks at the grid
// dependency sync until the reduce's writes are visible.
__global__ __launch_bounds__(THREADS)
void cm_finalize_kernel(float* __restrict__ out) {
    cudaGridDependencySynchronize();

    const int wid = threadIdx.x >> 5;
    const int lid = threadIdx.x & 31;

#pragma unroll
    for (int g = 0; g < SLICES / (THREADS / 32); g++) {
        const int s = g * (THREADS / 32) + wid;         // slice index
        const int idx = (s * BLOCKS_PER_SLICE + lid) * 3;
        float a = g_part[idx + 0];
        float b = g_part[idx + 1];
        float c = g_part[idx + 2];
#pragma unroll
        for (int off = 16; off > 0; off >>= 1) {
            a += __shfl_down_sync(0xFFFFFFFFu, a, off);
            b += __shfl_down_sync(0xFFFFFFFFu, b, off);
            c += __shfl_down_sync(0xFFFFFFFFu, c, off);
        }
        if (lid == 0) {
            const double da = a, db = b, dc = c;
            const double n = (double)N_PER_SLICE;
            out[s * 4 + 0] = (float)dc;                   // tp
            out[s * 4 + 1] = (float)(n - da - db + dc);   // tn
            out[s * 4 + 2] = (float)(da - dc);            // fp
            out[s * 4 + 3] = (float)(db - dc);            // fn
        }
    }
}

extern "C" void kernel_launch(void* const* d_in, const int* in_sizes, int n_in,
                              void* d_out, int out_size) {
    const float4* p4 = (const float4*)d_in[0];   // y_pred
    const float4* t4 = (const float4*)d_in[1];   // y_true
    float* out = (float*)d_out;

    cm_reduce_kernel<<<NBLOCKS, THREADS>>>(p4, t4);

    // PDL launch of the finalize: overlap its launch latency with the reduce.
    cudaLaunchConfig_t cfg = {};
    cfg.gridDim = dim3(1, 1, 1);
    cfg.blockDim = dim3(THREADS, 1, 1);
    cfg.dynamicSmemBytes = 0;
    cfg.stream = 0;  // same (captured) default stream as the <<<>>> launch
    cudaLaunchAttribute attrs[1];
    attrs[0].id = cudaLaunchAttributeProgrammaticStreamSerialization;
    attrs[0].val.programmaticStreamSerializationAllowed = 1;
    cfg.attrs = attrs;
    cfg.numAttrs = 1;
    cudaLaunchKernelEx(&cfg, cm_finalize_kernel, out);
}